// round 3
// baseline (speedup 1.0000x reference)
#include <cuda_runtime.h>

// Problem constants
#define NTOK 16384      // B*H*W = 16*32*32
#define KC   8192       // codebook entries
#define DD   256        // feature dim (= C)
#define IMG  262144     // C*H*W
#define HW   1024       // H*W

#define OUT_LOSS 4194304
#define OUT_ENC  4194305

// GEMM tiling
#define BM 128
#define BN 128
#define BK 16

// -------- scratch (device globals; no allocation allowed) --------
__device__ float g_cnorm[KC];
__device__ float g_xnorm[NTOK];
__device__ int   g_idx[NTOK];
__device__ float g_partial[NTOK / BM];

// -------- f32x2 packed helpers --------
union F2U { float2 f; unsigned long long u; };

__device__ __forceinline__ unsigned long long pack2(float v) {
    unsigned long long r;
    asm("mov.b64 %0, {%1, %1};" : "=l"(r) : "r"(__float_as_uint(v)));
    return r;
}
__device__ __forceinline__ void fma2(unsigned long long& d,
                                     unsigned long long a,
                                     unsigned long long b) {
    asm("fma.rn.f32x2 %0, %1, %2, %0;" : "+l"(d) : "l"(a), "l"(b));
}

// ============================================================
// Kernel 1: codebook squared norms.
// STRICT sequential chain: s = fl(s + fl(c*c)), d ascending.
// (emulates XLA-CPU jnp.sum(codebook*codebook, axis=1))
// ============================================================
__global__ __launch_bounds__(256) void cnorm_kernel(const float* __restrict__ cb) {
    int k = blockIdx.x * 256 + threadIdx.x;
    const float* p = cb + (size_t)k * DD;
    float s = 0.f;
#pragma unroll 8
    for (int d = 0; d < DD; ++d) {
        float v = p[d];
        s = __fadd_rn(s, __fmul_rn(v, v));
    }
    g_cnorm[k] = s;
}

// ============================================================
// Kernel 1b: token squared norms, same strict chain over C.
// token n=(b,hw): x[b*IMG + d*HW + hw]
// ============================================================
__global__ __launch_bounds__(256) void xnorm_kernel(const float* __restrict__ x) {
    int n  = blockIdx.x * 256 + threadIdx.x;
    int b  = n >> 10;
    int hw = n & (HW - 1);
    const float* p = x + (size_t)b * IMG + hw;
    float s = 0.f;
#pragma unroll 8
    for (int d = 0; d < DD; ++d) {
        float v = p[(size_t)d * HW];
        s = __fadd_rn(s, __fmul_rn(v, v));
    }
    g_xnorm[n] = s;
}

// ============================================================
// Kernel 2: fused distance GEMM + per-token argmin.
// m(n,k) = ascending-d fmaf chain (matches CPU GEMM micro-kernel order).
// dist   = fl( fl(xnorm + cnorm) - 2*m )   <-- reference rounding emulation
// argmin: first (lowest) index on exact rounded-value ties, like jnp.argmin.
// ============================================================
__global__ __launch_bounds__(256, 1) void dist_kernel(const float* __restrict__ x,
                                                      const float* __restrict__ cb) {
    __shared__ float As[BK][BM];        // [d][token]
    __shared__ float Bs[BK][BN + 4];    // [d][code]
    __shared__ float Rv[BM][17];
    __shared__ int   Ri[BM][17];

    const int tid = threadIdx.x;
    const int tx  = tid & 15;
    const int ty  = tid >> 4;
    const int ty8 = ty * 8;

    const int tok0 = blockIdx.x * BM;
    const int bimg = tok0 >> 10;
    const int hw0  = tok0 & (HW - 1);
    const float* xb = x + (size_t)bimg * IMG + hw0;

    // loader indices
    const int lr = tid >> 5;            // 0..7 : d-row for A
    const int lc = (tid & 31) * 4;      // 0..124 : token col (float4)
    const int br = tid & 127;           // code row for B
    const int bd = (tid >> 7) * 8;      // 0 or 8 : d offset for B

    // token norms for this thread's 8 rows
    float xr[8];
#pragma unroll
    for (int i = 0; i < 8; ++i) xr[i] = g_xnorm[tok0 + ty8 + i];

    float bestv[8];
    int   besti[8];
#pragma unroll
    for (int i = 0; i < 8; ++i) { bestv[i] = 3.4e38f; besti[i] = 0; }

    for (int k0 = 0; k0 < KC; k0 += BN) {
        unsigned long long acc[4][8];
#pragma unroll
        for (int i = 0; i < 4; ++i)
#pragma unroll
            for (int j = 0; j < 8; ++j) acc[i][j] = 0ull;

        for (int d0 = 0; d0 < DD; d0 += BK) {
            // prefetch global
            float4 v0 = *(const float4*)(xb + (size_t)(d0 + lr) * HW + lc);
            float4 v1 = *(const float4*)(xb + (size_t)(d0 + lr + 8) * HW + lc);
            const float* cp = cb + (size_t)(k0 + br) * DD + d0 + bd;
            float4 u0 = *(const float4*)cp;
            float4 u1 = *(const float4*)(cp + 4);

            __syncthreads();
            *(float4*)&As[lr][lc]     = v0;
            *(float4*)&As[lr + 8][lc] = v1;
            Bs[bd + 0][br] = u0.x; Bs[bd + 1][br] = u0.y;
            Bs[bd + 2][br] = u0.z; Bs[bd + 3][br] = u0.w;
            Bs[bd + 4][br] = u1.x; Bs[bd + 5][br] = u1.y;
            Bs[bd + 6][br] = u1.z; Bs[bd + 7][br] = u1.w;
            __syncthreads();

#pragma unroll
            for (int dk = 0; dk < BK; ++dk) {
                const unsigned long long* a64 =
                    reinterpret_cast<const unsigned long long*>(&As[dk][ty8]);
                unsigned long long A0 = a64[0], A1 = a64[1], A2 = a64[2], A3 = a64[3];
#pragma unroll
                for (int j = 0; j < 8; ++j) {
                    unsigned long long B = pack2(Bs[dk][tx + 16 * j]);
                    fma2(acc[0][j], A0, B);
                    fma2(acc[1][j], A1, B);
                    fma2(acc[2][j], A2, B);
                    fma2(acc[3][j], A3, B);
                }
            }
        }

        // reference-rounded distances + running argmin
        // k ascends with chunk then j -> strict '<' keeps first index
#pragma unroll
        for (int j = 0; j < 8; ++j) {
            int   k  = k0 + 16 * j + tx;
            float cn = g_cnorm[k];
#pragma unroll
            for (int i = 0; i < 4; ++i) {
                F2U t; t.u = acc[i][j];
                // S = fl(xnorm + cnorm); d = fl(S - 2*m)  (2*m exact)
                float s0  = __fadd_rn(xr[2 * i],     cn);
                float s1  = __fadd_rn(xr[2 * i + 1], cn);
                float dlo = __fsub_rn(s0, 2.0f * t.f.x);
                float dhi = __fsub_rn(s1, 2.0f * t.f.y);
                if (dlo < bestv[2 * i])     { bestv[2 * i]     = dlo; besti[2 * i]     = k; }
                if (dhi < bestv[2 * i + 1]) { bestv[2 * i + 1] = dhi; besti[2 * i + 1] = k; }
            }
        }
    }

    // cross-thread (tx) reduction per token row; lowest index on ties
#pragma unroll
    for (int i = 0; i < 8; ++i) {
        Rv[ty8 + i][tx] = bestv[i];
        Ri[ty8 + i][tx] = besti[i];
    }
    __syncthreads();
    if (tid < BM) {
        float bv = Rv[tid][0];
        int   bi = Ri[tid][0];
#pragma unroll
        for (int t = 1; t < 16; ++t) {
            float v  = Rv[tid][t];
            int   ii = Ri[tid][t];
            if (v < bv || (v == bv && ii < bi)) { bv = v; bi = ii; }
        }
        g_idx[tok0 + tid] = bi;
    }
}

// ============================================================
// Kernel 3: gather quant, straight-through output, loss partial.
// ST emulation: out = fl(x + fl(q - x))  (matches xp + stopgrad(quant - xp))
// ============================================================
__global__ __launch_bounds__(256) void epi_kernel(const float* __restrict__ x,
                                                  const float* __restrict__ cb,
                                                  float* __restrict__ out) {
    __shared__ int   sidx[128];
    __shared__ float swarp[8];

    const int tid  = threadIdx.x;
    const int tok0 = blockIdx.x * 128;
    const int bimg = tok0 >> 10;
    const int hw0  = tok0 & (HW - 1);

    if (tid < 128) sidx[tid] = g_idx[tok0 + tid];
    __syncthreads();

    const int m  = tid & 127;
    const int dh = tid >> 7;                 // 0 or 1
    const size_t base = (size_t)bimg * IMG + hw0 + m;
    const long long crow = (long long)sidx[m] * DD;

    float lsum = 0.f;
#pragma unroll 8
    for (int d0 = 0; d0 < DD; d0 += 2) {
        int d = d0 + dh;
        float q  = cb[crow + d];
        size_t off = base + (size_t)d * HW;
        float xv = x[off];
        float t  = __fsub_rn(q, xv);        // fl(q - x)
        out[off] = __fadd_rn(xv, t);        // fl(x + fl(q - x))
        lsum = fmaf(t, t, lsum);
    }

#pragma unroll
    for (int off = 16; off; off >>= 1) lsum += __shfl_xor_sync(0xffffffffu, lsum, off);
    if ((tid & 31) == 0) swarp[tid >> 5] = lsum;
    __syncthreads();
    if (tid == 0) {
        float s = 0.f;
        for (int w = 0; w < 8; ++w) s += swarp[w];
        g_partial[blockIdx.x] = s;          // fixed-order -> deterministic
    }
    if (tid < 128) out[OUT_ENC + tok0 + tid] = (float)sidx[tid];
}

// ============================================================
// Kernel 4: finalize loss (deterministic tree over 128 partials)
// ============================================================
__global__ __launch_bounds__(128) void fin_kernel(float* __restrict__ out) {
    __shared__ float sw[4];
    int tid = threadIdx.x;
    float s = g_partial[tid];
#pragma unroll
    for (int off = 16; off; off >>= 1) s += __shfl_xor_sync(0xffffffffu, s, off);
    if ((tid & 31) == 0) sw[tid >> 5] = s;
    __syncthreads();
    if (tid == 0) {
        float mse = (sw[0] + sw[1] + sw[2] + sw[3]) / 4194304.0f;
        // q_latent == e_latent in forward; vq = mse + 0.25*mse
        out[OUT_LOSS] = __fadd_rn(mse, __fmul_rn(0.25f, mse));
    }
}

// ============================================================
extern "C" void kernel_launch(void* const* d_in, const int* in_sizes, int n_in,
                              void* d_out, int out_size) {
    const float* x  = (const float*)d_in[0];   // [16,256,32,32] fp32
    const float* cb = (const float*)d_in[1];   // [8192,256] fp32
    float* out = (float*)d_out;                // [quant | loss | encodings] fp32

    cnorm_kernel<<<KC / 256, 256>>>(cb);
    xnorm_kernel<<<NTOK / 256, 256>>>(x);
    dist_kernel<<<NTOK / BM, 256>>>(x, cb);
    epi_kernel<<<NTOK / 128, 256>>>(x, cb, out);
    fin_kernel<<<1, 128>>>(out);
}

// round 4
// speedup vs baseline: 1.2354x; 1.2354x over previous
#include <cuda_runtime.h>

// Problem constants
#define NTOK 16384      // B*H*W = 16*32*32
#define KC   8192       // codebook entries
#define DD   256        // feature dim (= C)
#define IMG  262144     // C*H*W
#define HW   1024       // H*W

#define OUT_LOSS 4194304
#define OUT_ENC  4194305

// GEMM tiling
#define BM 128
#define BN 256
#define BK 16
#define ASTR 132        // As row stride (floats): 16B-aligned rows
#define BSTR 258        // Bs row stride (floats): makes transpose STS conflict-free

// -------- scratch (device globals; no allocation allowed) --------
__device__ float g_cnorm[KC];
__device__ float g_xnorm[NTOK];
__device__ int   g_idx[NTOK];
__device__ float g_partial[256];

// -------- f32x2 packed helpers --------
union F2U { float2 f; unsigned long long u; };

__device__ __forceinline__ unsigned long long pack2(float v) {
    unsigned long long r;
    asm("mov.b64 %0, {%1, %1};" : "=l"(r) : "r"(__float_as_uint(v)));
    return r;
}
__device__ __forceinline__ void fma2(unsigned long long& d,
                                     unsigned long long a,
                                     unsigned long long b) {
    asm("fma.rn.f32x2 %0, %1, %2, %0;" : "+l"(d) : "l"(a), "l"(b));
}
__device__ __forceinline__ unsigned long long fma2_3(unsigned long long a,
                                                     unsigned long long b,
                                                     unsigned long long c) {
    unsigned long long d;
    asm("fma.rn.f32x2 %0, %1, %2, %3;" : "=l"(d) : "l"(a), "l"(b), "l"(c));
    return d;
}
__device__ __forceinline__ unsigned long long add2(unsigned long long a,
                                                   unsigned long long b) {
    unsigned long long d;
    asm("add.rn.f32x2 %0, %1, %2;" : "=l"(d) : "l"(a), "l"(b));
    return d;
}

// ============================================================
// Kernel 1: norms (codebook + tokens), strict sequential chains
// s = fl(s + fl(v*v)), d ascending  — bit-exact vs XLA-CPU sum.
// blocks 0..31: cnorm (8192 rows); blocks 32..95: xnorm (16384 tokens)
// ============================================================
__global__ __launch_bounds__(256) void norms_kernel(const float* __restrict__ x,
                                                    const float* __restrict__ cb) {
    int blk = blockIdx.x;
    if (blk < 32) {
        int k = blk * 256 + threadIdx.x;
        const float* p = cb + (size_t)k * DD;
        float s = 0.f;
#pragma unroll 8
        for (int d = 0; d < DD; ++d) {
            float v = p[d];
            s = __fadd_rn(s, __fmul_rn(v, v));
        }
        g_cnorm[k] = s;
    } else {
        int n  = (blk - 32) * 256 + threadIdx.x;
        int b  = n >> 10;
        int hw = n & (HW - 1);
        const float* p = x + (size_t)b * IMG + hw;
        float s = 0.f;
#pragma unroll 8
        for (int d = 0; d < DD; ++d) {
            float v = p[(size_t)d * HW];
            s = __fadd_rn(s, __fmul_rn(v, v));
        }
        g_xnorm[n] = s;
    }
}

// ============================================================
// Kernel 2: fused distance GEMM + per-token argmin.
// 512 threads. Block tile 128x256, thread tile 8 tokens x 8 codes.
// Warp = fixed token-group (tg), lanes span codes (cx + 32*j).
// Tokens PACKED in f32x2 (As holds token values, read as u64 pairs).
// Bs filled with COALESCED gmem reads + conflict-free transpose STS.
// Smem double-buffered: one __syncthreads per BK step.
// dist = fl( fl(xnorm+cnorm) - 2*m ) via fma.f32x2(m, -2, S): bit-exact.
// ============================================================
__global__ __launch_bounds__(512, 1) void dist_kernel(const float* __restrict__ x,
                                                      const float* __restrict__ cb) {
    __shared__ float As[2][BK][ASTR];
    __shared__ float Bs[2][BK][BSTR];

    const int tid = threadIdx.x;
    const int cx  = tid & 31;           // code lane 0..31
    const int tg  = tid >> 5;           // token group 0..15 (= warp id)
    const int tg8 = tg * 8;

    const int tok0 = blockIdx.x * BM;
    const int bimg = tok0 >> 10;
    const int hw0  = tok0 & (HW - 1);
    const float* xb = x + (size_t)bimg * IMG + hw0;

    // A loader: one float4; d-row = warp, tokens consecutive (coalesced)
    const int ad  = tid >> 5;           // 0..15
    const int at4 = (tid & 31) * 4;     // 0..124
    // B loader: coalesced float2 per row; 4 rows per thread
    const int bro = tid >> 3;           // 0..63 (row base; +64*i)
    const int bd  = (tid & 7) * 2;      // d-pair 0,2,..,14

    const unsigned long long NEG2 = pack2(-2.0f);

    float bestv[8];
    int   besti[8];
#pragma unroll
    for (int i = 0; i < 8; ++i) { bestv[i] = 3.4e38f; besti[i] = 0; }

    for (int k0 = 0; k0 < KC; k0 += BN) {
        unsigned long long acc[4][8];
#pragma unroll
        for (int i = 0; i < 4; ++i)
#pragma unroll
            for (int j = 0; j < 8; ++j) acc[i][j] = 0ull;

        // ---- preload d0 = 0 into buffer 0 ----
        {
            float4 av = *(const float4*)(xb + (size_t)ad * HW + at4);
            float2 bv0 = *(const float2*)(cb + (size_t)(k0 + bro      ) * DD + bd);
            float2 bv1 = *(const float2*)(cb + (size_t)(k0 + bro +  64) * DD + bd);
            float2 bv2 = *(const float2*)(cb + (size_t)(k0 + bro + 128) * DD + bd);
            float2 bv3 = *(const float2*)(cb + (size_t)(k0 + bro + 192) * DD + bd);
            *(float4*)&As[0][ad][at4] = av;
            Bs[0][bd][bro]           = bv0.x; Bs[0][bd + 1][bro]       = bv0.y;
            Bs[0][bd][bro + 64]      = bv1.x; Bs[0][bd + 1][bro + 64]  = bv1.y;
            Bs[0][bd][bro + 128]     = bv2.x; Bs[0][bd + 1][bro + 128] = bv2.y;
            Bs[0][bd][bro + 192]     = bv3.x; Bs[0][bd + 1][bro + 192] = bv3.y;
        }
        __syncthreads();

        for (int d0i = 0; d0i < BK; ++d0i) {   // 16 steps of 16 d's each
            const int cur = d0i & 1;
            const int d0n = (d0i + 1) * BK;

            // prefetch next step into registers
            float4 av; float2 bv0, bv1, bv2, bv3;
            if (d0i < BK - 1) {
                av  = *(const float4*)(xb + (size_t)(d0n + ad) * HW + at4);
                bv0 = *(const float2*)(cb + (size_t)(k0 + bro      ) * DD + d0n + bd);
                bv1 = *(const float2*)(cb + (size_t)(k0 + bro +  64) * DD + d0n + bd);
                bv2 = *(const float2*)(cb + (size_t)(k0 + bro + 128) * DD + d0n + bd);
                bv3 = *(const float2*)(cb + (size_t)(k0 + bro + 192) * DD + d0n + bd);
            }

            // compute 16 dk from current buffer (ascending d: bit-exact chain)
#pragma unroll
            for (int dk = 0; dk < BK; ++dk) {
                const unsigned long long* a64 =
                    reinterpret_cast<const unsigned long long*>(&As[cur][dk][tg8]);
                unsigned long long A0 = a64[0], A1 = a64[1], A2 = a64[2], A3 = a64[3];
#pragma unroll
                for (int j = 0; j < 8; ++j) {
                    unsigned long long B = pack2(Bs[cur][dk][cx + 32 * j]);
                    fma2(acc[0][j], A0, B);
                    fma2(acc[1][j], A1, B);
                    fma2(acc[2][j], A2, B);
                    fma2(acc[3][j], A3, B);
                }
            }

            if (d0i < BK - 1) {
                const int nxt = cur ^ 1;
                *(float4*)&As[nxt][ad][at4] = av;
                Bs[nxt][bd][bro]           = bv0.x; Bs[nxt][bd + 1][bro]       = bv0.y;
                Bs[nxt][bd][bro + 64]      = bv1.x; Bs[nxt][bd + 1][bro + 64]  = bv1.y;
                Bs[nxt][bd][bro + 128]     = bv2.x; Bs[nxt][bd + 1][bro + 128] = bv2.y;
                Bs[nxt][bd][bro + 192]     = bv3.x; Bs[nxt][bd + 1][bro + 192] = bv3.y;
                __syncthreads();
            }
        }

        // ---- chunk epilogue: reference-rounded distances + running argmin ----
        // token-pair xnorms (packed), reloaded per chunk to save registers
        unsigned long long xp2[4];
#pragma unroll
        for (int i = 0; i < 4; ++i)
            xp2[i] = *(const unsigned long long*)&g_xnorm[tok0 + tg8 + 2 * i];

#pragma unroll
        for (int j = 0; j < 8; ++j) {
            int   k  = k0 + cx + 32 * j;
            unsigned long long cn2 = pack2(g_cnorm[k]);
#pragma unroll
            for (int i = 0; i < 4; ++i) {
                // S = fl(xnorm + cnorm); d = fl(S - 2*m) == fma(m, -2, S)
                unsigned long long S2 = add2(xp2[i], cn2);
                F2U D; D.u = fma2_3(acc[i][j], NEG2, S2);
                if (D.f.x < bestv[2 * i])     { bestv[2 * i]     = D.f.x; besti[2 * i]     = k; }
                if (D.f.y < bestv[2 * i + 1]) { bestv[2 * i + 1] = D.f.y; besti[2 * i + 1] = k; }
            }
        }
        __syncthreads();   // before next chunk's preload overwrites buffer 0
    }

    // warp-level argmin reduce across the 32 code-lanes (tie -> lowest index)
#pragma unroll
    for (int i = 0; i < 8; ++i) {
        float bv = bestv[i];
        int   bi = besti[i];
#pragma unroll
        for (int off = 16; off; off >>= 1) {
            float ov = __shfl_xor_sync(0xffffffffu, bv, off);
            int   ob = __shfl_xor_sync(0xffffffffu, bi, off);
            if (ov < bv || (ov == bv && ob < bi)) { bv = ov; bi = ob; }
        }
        if (cx == 0) g_idx[tok0 + tg8 + i] = bi;
    }
}

// ============================================================
// Kernel 3: gather quant, straight-through output, loss partial.
// 256 blocks x 64 tokens. out = fl(x + fl(q - x)).
// ============================================================
__global__ __launch_bounds__(256) void epi_kernel(const float* __restrict__ x,
                                                  const float* __restrict__ cb,
                                                  float* __restrict__ out) {
    __shared__ int   sidx[64];
    __shared__ float swarp[8];

    const int tid  = threadIdx.x;
    const int tok0 = blockIdx.x * 64;
    const int bimg = tok0 >> 10;
    const int hw0  = tok0 & (HW - 1);

    if (tid < 64) sidx[tid] = g_idx[tok0 + tid];
    __syncthreads();

    const int m  = tid & 63;
    const int dh = tid >> 6;                 // 0..3
    const size_t base = (size_t)bimg * IMG + hw0 + m;
    const long long crow = (long long)sidx[m] * DD;

    float lsum = 0.f;
#pragma unroll 8
    for (int d0 = 0; d0 < DD; d0 += 4) {
        int d = d0 + dh;
        float q  = cb[crow + d];
        size_t off = base + (size_t)d * HW;
        float xv = x[off];
        float t  = __fsub_rn(q, xv);        // fl(q - x)
        out[off] = __fadd_rn(xv, t);        // fl(x + fl(q - x))
        lsum = fmaf(t, t, lsum);
    }

#pragma unroll
    for (int off = 16; off; off >>= 1) lsum += __shfl_xor_sync(0xffffffffu, lsum, off);
    if ((tid & 31) == 0) swarp[tid >> 5] = lsum;
    __syncthreads();
    if (tid == 0) {
        float s = 0.f;
        for (int w = 0; w < 8; ++w) s += swarp[w];
        g_partial[blockIdx.x] = s;          // fixed-order -> deterministic
    }
    if (tid < 64) out[OUT_ENC + tok0 + tid] = (float)sidx[tid];
}

// ============================================================
// Kernel 4: finalize loss (deterministic tree over 256 partials)
// ============================================================
__global__ __launch_bounds__(256) void fin_kernel(float* __restrict__ out) {
    __shared__ float sw[8];
    int tid = threadIdx.x;
    float s = g_partial[tid];
#pragma unroll
    for (int off = 16; off; off >>= 1) s += __shfl_xor_sync(0xffffffffu, s, off);
    if ((tid & 31) == 0) sw[tid >> 5] = s;
    __syncthreads();
    if (tid == 0) {
        float tot = 0.f;
        for (int w = 0; w < 8; ++w) tot += sw[w];
        float mse = tot / 4194304.0f;
        // q_latent == e_latent in forward; vq = mse + 0.25*mse
        out[OUT_LOSS] = __fadd_rn(mse, __fmul_rn(0.25f, mse));
    }
}

// ============================================================
extern "C" void kernel_launch(void* const* d_in, const int* in_sizes, int n_in,
                              void* d_out, int out_size) {
    const float* x  = (const float*)d_in[0];   // [16,256,32,32] fp32
    const float* cb = (const float*)d_in[1];   // [8192,256] fp32
    float* out = (float*)d_out;                // [quant | loss | encodings] fp32

    norms_kernel<<<96, 256>>>(x, cb);
    dist_kernel<<<NTOK / BM, 512>>>(x, cb);
    epi_kernel<<<256, 256>>>(x, cb, out);
    fin_kernel<<<1, 256>>>(out);
}